// round 11
// baseline (speedup 1.0000x reference)
#include <cuda_runtime.h>
#include <cuda_fp16.h>
#include <cstdint>
#include <cstddef>

#define G_   128
#define M_   512
#define D_   512
#define MA   513
#define NORM_C (1.0f/1024.0f)

// ---------------- scratch ----------------
__device__ __align__(16) __half g_Ah[(size_t)G_ * M_ * D_];   // normalized tra fp16
__device__ __align__(16) __half g_Bh[(size_t)G_ * M_ * D_];   // normalized det fp16

// ---------------- helpers ----------------
__device__ __forceinline__ uint32_t pack_h2(float lo, float hi) {
    uint32_t r; asm("cvt.rn.f16x2.f32 %0, %1, %2;" : "=r"(r) : "f"(hi), "f"(lo)); return r;
}
__device__ __forceinline__ uint32_t s2u(const void* p) {
    return (uint32_t)__cvta_generic_to_shared(p);
}
__device__ __forceinline__ void cp16(uint32_t saddr, const void* g) {
    asm volatile("cp.async.cg.shared.global [%0], [%1], 16;" :: "r"(saddr), "l"(g));
}
__device__ __forceinline__ void ldsm4(uint32_t* r, uint32_t a) {
    asm volatile("ldmatrix.sync.aligned.m8n8.x4.shared.b16 {%0,%1,%2,%3}, [%4];"
                 : "=r"(r[0]), "=r"(r[1]), "=r"(r[2]), "=r"(r[3]) : "r"(a));
}
__device__ __forceinline__ void cvt8(uint4 d0, uint4 d1, float2* e) {
    e[0] = __half22float2(*reinterpret_cast<__half2*>(&d0.x));
    e[1] = __half22float2(*reinterpret_cast<__half2*>(&d0.y));
    e[2] = __half22float2(*reinterpret_cast<__half2*>(&d0.z));
    e[3] = __half22float2(*reinterpret_cast<__half2*>(&d0.w));
    e[4] = __half22float2(*reinterpret_cast<__half2*>(&d1.x));
    e[5] = __half22float2(*reinterpret_cast<__half2*>(&d1.y));
    e[6] = __half22float2(*reinterpret_cast<__half2*>(&d1.z));
    e[7] = __half22float2(*reinterpret_cast<__half2*>(&d1.w));
}
__device__ __forceinline__ uint32_t ctarank() {
    uint32_t r; asm("mov.u32 %0, %%cluster_ctarank;" : "=r"(r)); return r;
}
__device__ __forceinline__ uint32_t mapa_u32(uint32_t addr, uint32_t rank) {
    uint32_t r; asm("mapa.shared::cluster.u32 %0, %1, %2;" : "=r"(r) : "r"(addr), "r"(rank));
    return r;
}
__device__ __forceinline__ float ld_dsmem(uint32_t addr) {
    float v; asm volatile("ld.shared::cluster.f32 %0, [%1];" : "=f"(v) : "r"(addr));
    return v;
}
#define CLUSTER_SYNC() do { \
    asm volatile("barrier.cluster.arrive.aligned;" ::: "memory"); \
    asm volatile("barrier.cluster.wait.aligned;" ::: "memory"); } while (0)

// ---------------- normalize + fp16 convert ----------------
__global__ void __launch_bounds__(256) normalize_kernel(const float* __restrict__ tra,
                                                        const float* __restrict__ det) {
    const float* x = blockIdx.y ? det : tra;
    __half* out = blockIdx.y ? g_Bh : g_Ah;
    int warp = threadIdx.x >> 5, lane = threadIdx.x & 31;
    int row = blockIdx.x * 8 + warp;
    const float4* p = reinterpret_cast<const float4*>(x + (size_t)row * D_);
    float4 v[4];
    float s = 0.f;
#pragma unroll
    for (int k = 0; k < 4; ++k) {
        v[k] = p[lane + k * 32];
        s += v[k].x * v[k].x + v[k].y * v[k].y + v[k].z * v[k].z + v[k].w * v[k].w;
    }
#pragma unroll
    for (int o = 16; o > 0; o >>= 1) s += __shfl_xor_sync(0xffffffffu, s, o);
    float inv = rsqrtf(s);
    uint2* po = reinterpret_cast<uint2*>(out + (size_t)row * D_);
#pragma unroll
    for (int k = 0; k < 4; ++k) {
        uint2 h;
        h.x = pack_h2(v[k].x * inv, v[k].y * inv);
        h.y = pack_h2(v[k].z * inv, v[k].w * inv);
        po[lane + k * 32] = h;
    }
}

// ---------------- fused GEMM + Sinkhorn + output, one 4-CTA cluster per graph ----------------
#define BK 32
#define ROWH 40
#define TB 10240                       // bytes per staged 128x32 tile (128*40*2)
#define E_LD 520                       // E strip leading dim in halves (1040 B, +4 bank shift/row)
#define OFF_E     0
#define E_BYTES   (128 * E_LD * 2)     // 133120
#define OFF_STAGE E_BYTES              // gemm: 4 tiles (2 bufs x A,B) = 40960 B; sinkhorn: scol 32768 B
#define OFF_CPART (OFF_STAGE + 40960)  // 174080: CTA partial colsum [512]
#define OFF_WSUM  (OFF_CPART + 2048)   // 176128: CTA wsum scalar (DSMEM-read)
#define OFF_SV    (OFF_WSUM + 16)      // 176144: v[520]
#define OFF_SWSUM (OFF_SV + 2080)      // 178224: per-warp wsum [16]
#define OFF_SSCAL (OFF_SWSUM + 64)     // 178288
#define SMEM_TOTAL (OFF_SSCAL + 32)    // 178320 B

__global__ void __launch_bounds__(512, 1) __cluster_dims__(4, 1, 1)
fused_kernel(float* __restrict__ out, const float* __restrict__ alpha,
             const float* __restrict__ eps)
{
    extern __shared__ char sm[];
    const uint32_t sb = s2u(sm);
    __half* E    = reinterpret_cast<__half*>(sm);
    float* scol  = reinterpret_cast<float*>(sm + OFF_STAGE);
    float* cpart = reinterpret_cast<float*>(sm + OFF_CPART);
    float* wsumP = reinterpret_cast<float*>(sm + OFF_WSUM);
    float* sv    = reinterpret_cast<float*>(sm + OFF_SV);
    float* swsum = reinterpret_cast<float*>(sm + OFF_SWSUM);
    float* sscal = reinterpret_cast<float*>(sm + OFF_SSCAL);

    const int tid = threadIdx.x, lane = tid & 31, warp = tid >> 5;
    const int g = blockIdx.y;
    const uint32_t rank = ctarank();             // == blockIdx.x
    const float invL = 1.f / (__expf(eps[0]) + 0.03f);
    const float c = __expf(-alpha[0] * invL);
    const float AB512 = NORM_C * 512.f;

    // ================= Phase 1: GEMM, E strip (128 x 512) into SMEM =================
    {
        const int wm = warp >> 2, wn = warp & 3;     // 4x4 warps, warp tile 32x32
        const int grp = lane >> 2, tig = lane & 3;
        const int aRow = (((lane >> 3) & 1) << 3) + (lane & 7);
        const int aCol = ((lane >> 4) << 3);
        const int bRow = ((lane >> 4) << 3) + (lane & 7);
        const int bCol = (((lane >> 3) & 1) << 3);
        const int lrow = tid >> 2, lc = tid & 3;     // 512 thr -> 128 rows x 4 chunks
        const __half* gA = g_Ah + ((size_t)g * M_ + rank * 128) * D_;

        for (int qn = 0; qn < 4; ++qn) {
            const __half* gB = g_Bh + ((size_t)g * M_ + qn * 128) * D_;
            auto load = [&](int kc, int buf) {
                const uint32_t sa = sb + OFF_STAGE + buf * (2 * TB);
                cp16(sa + (lrow * ROWH + lc * 8) * 2,
                     gA + (size_t)lrow * D_ + kc * BK + lc * 8);
                cp16(sa + TB + (lrow * ROWH + lc * 8) * 2,
                     gB + (size_t)lrow * D_ + kc * BK + lc * 8);
                asm volatile("cp.async.commit_group;" ::: "memory");
            };
            float acc[2][4][4];
#pragma unroll
            for (int a = 0; a < 2; ++a)
#pragma unroll
                for (int b = 0; b < 4; ++b)
#pragma unroll
                    for (int d = 0; d < 4; ++d) acc[a][b][d] = 0.f;

            load(0, 0);
            for (int kt = 0; kt < 16; ++kt) {
                asm volatile("cp.async.wait_group 0;" ::: "memory");
                __syncthreads();
                if (kt + 1 < 16) load(kt + 1, (kt + 1) & 1);
                const uint32_t ab = sb + OFF_STAGE + (kt & 1) * (2 * TB);
                const uint32_t bb = ab + TB;
#pragma unroll
                for (int ks = 0; ks < 2; ++ks) {
                    uint32_t af[2][4], bf[2][4];
#pragma unroll
                    for (int mt = 0; mt < 2; ++mt)
                        ldsm4(af[mt], ab + ((wm * 32 + mt * 16 + aRow) * ROWH + ks * 16 + aCol) * 2);
#pragma unroll
                    for (int p = 0; p < 2; ++p)
                        ldsm4(bf[p], bb + ((wn * 32 + p * 16 + bRow) * ROWH + ks * 16 + bCol) * 2);
#pragma unroll
                    for (int mt = 0; mt < 2; ++mt)
#pragma unroll
                        for (int nt = 0; nt < 4; ++nt)
                            asm volatile(
                                "mma.sync.aligned.m16n8k16.row.col.f32.f16.f16.f32 "
                                "{%0,%1,%2,%3}, {%4,%5,%6,%7}, {%8,%9}, {%0,%1,%2,%3};"
                                : "+f"(acc[mt][nt][0]), "+f"(acc[mt][nt][1]),
                                  "+f"(acc[mt][nt][2]), "+f"(acc[mt][nt][3])
                                : "r"(af[mt][0]), "r"(af[mt][1]), "r"(af[mt][2]), "r"(af[mt][3]),
                                  "r"(bf[nt >> 1][(nt & 1) * 2]), "r"(bf[nt >> 1][(nt & 1) * 2 + 1]));
                }
            }
            // epilogue: E = exp(-dot * invL) -> fp16 strip in SMEM
#pragma unroll
            for (int mt = 0; mt < 2; ++mt) {
                int row = wm * 32 + mt * 16 + grp;
#pragma unroll
                for (int nt = 0; nt < 4; ++nt) {
                    int col = qn * 128 + wn * 32 + nt * 8 + 2 * tig;
                    *reinterpret_cast<uint32_t*>(&E[row * E_LD + col]) =
                        pack_h2(__expf(-acc[mt][nt][0] * invL), __expf(-acc[mt][nt][1] * invL));
                    *reinterpret_cast<uint32_t*>(&E[(row + 8) * E_LD + col]) =
                        pack_h2(__expf(-acc[mt][nt][2] * invL), __expf(-acc[mt][nt][3] * invL));
                }
            }
            __syncthreads();
        }
    }

    // ================= Phase 2: Sinkhorn (8 iters) + output =================
    // warp w owns local rows [w*8, w*8+8); lane owns cols lane*8.. and 256+lane*8..
    auto read_row = [&](int lr, float2* e) {
        const char* p = sm + lr * (E_LD * 2) + lane * 16;
        uint4 d0 = *reinterpret_cast<const uint4*>(p);
        uint4 d1 = *reinterpret_cast<const uint4*>(p + 512);
        cvt8(d0, d1, e);
    };
    float2 e[8], vr[8];
    const int lr0 = warp * 8;
    const uint32_t pr1 = (rank + 1) & 3, pr2 = (rank + 2) & 3, pr3 = (rank + 3) & 3;

    // ---- pass 0: column sums with u == 1 ----
    {
        float2 ca[8];
#pragma unroll
        for (int q = 0; q < 8; ++q) ca[q] = make_float2(0.f, 0.f);
#pragma unroll
        for (int t = 0; t < 8; ++t) {
            read_row(lr0 + t, e);
#pragma unroll
            for (int q = 0; q < 8; ++q) { ca[q].x += e[q].x; ca[q].y += e[q].y; }
        }
        float* d0 = scol + warp * 512 + lane * 8;
        float* d1 = d0 + 256;
#pragma unroll
        for (int q = 0; q < 4; ++q) {
            d0[2 * q] = ca[q].x;     d0[2 * q + 1] = ca[q].y;
            d1[2 * q] = ca[q + 4].x; d1[2 * q + 1] = ca[q + 4].y;
        }
    }
    __syncthreads();
    {
        float s = 0.f;
#pragma unroll
        for (int ww = 0; ww < 16; ++ww) s += scol[ww * 512 + tid];
        cpart[tid] = s;
    }
    CLUSTER_SYNC();
    {
        float t1 = ld_dsmem(mapa_u32(sb + OFF_CPART + tid * 4, pr1));
        float t2 = ld_dsmem(mapa_u32(sb + OFF_CPART + tid * 4, pr2));
        float t3 = ld_dsmem(mapa_u32(sb + OFF_CPART + tid * 4, pr3));
        float s = cpart[tid] + t1 + t2 + t3 + c;       // bin row, u512 = 1
        sv[tid] = __fdividef(NORM_C, s);
        if (tid == 0) sv[512] = __fdividef(AB512, c * 513.f);
    }
    __syncthreads();
    if (warp == 0) {
        float p = 0.f;
#pragma unroll
        for (int k = 0; k < 16; ++k) p += sv[lane + 32 * k];
#pragma unroll
        for (int o = 16; o > 0; o >>= 1) p += __shfl_xor_sync(0xffffffffu, p, o);
        if (lane == 0) sscal[0] = __fdividef(AB512, c * (p + sv[512]));
    }
    CLUSTER_SYNC();

    // ---- 7 fused iterations ----
    for (int it = 0; it < 7; ++it) {
#pragma unroll
        for (int q = 0; q < 4; ++q) {
            vr[q]     = *reinterpret_cast<float2*>(&sv[lane * 8 + 2 * q]);
            vr[q + 4] = *reinterpret_cast<float2*>(&sv[256 + lane * 8 + 2 * q]);
        }
        const float v512 = sv[512];
        const float u512 = sscal[0];
        float2 ca[8];
#pragma unroll
        for (int q = 0; q < 8; ++q) ca[q] = make_float2(0.f, 0.f);
        float wsum = 0.f;
#pragma unroll
        for (int b = 0; b < 2; ++b) {
            float rs[4];
#pragma unroll
            for (int r = 0; r < 4; ++r) {
                read_row(lr0 + b * 4 + r, e);
                float s = 0.f;
#pragma unroll
                for (int q = 0; q < 8; ++q) s += e[q].x * vr[q].x + e[q].y * vr[q].y;
                rs[r] = s;
            }
#pragma unroll
            for (int o = 16; o > 0; o >>= 1)
#pragma unroll
                for (int r = 0; r < 4; ++r) rs[r] += __shfl_xor_sync(0xffffffffu, rs[r], o);
#pragma unroll
            for (int r = 0; r < 4; ++r) {
                float u = __fdividef(NORM_C, rs[r] + c * v512);
                wsum += u;
                read_row(lr0 + b * 4 + r, e);
#pragma unroll
                for (int q = 0; q < 8; ++q) { ca[q].x += u * e[q].x; ca[q].y += u * e[q].y; }
            }
        }
        {
            float* d0 = scol + warp * 512 + lane * 8;
            float* d1 = d0 + 256;
#pragma unroll
            for (int q = 0; q < 4; ++q) {
                d0[2 * q] = ca[q].x;     d0[2 * q + 1] = ca[q].y;
                d1[2 * q] = ca[q + 4].x; d1[2 * q + 1] = ca[q + 4].y;
            }
        }
        if (lane == 0) swsum[warp] = wsum;
        __syncthreads();
        {
            float s = 0.f;
#pragma unroll
            for (int ww = 0; ww < 16; ++ww) s += scol[ww * 512 + tid];
            cpart[tid] = s;
            if (tid == 0) {
                float sU = 0.f;
#pragma unroll
                for (int ww = 0; ww < 16; ++ww) sU += swsum[ww];
                wsumP[0] = sU;
            }
        }
        CLUSTER_SYNC();
        {
            float t1 = ld_dsmem(mapa_u32(sb + OFF_CPART + tid * 4, pr1));
            float t2 = ld_dsmem(mapa_u32(sb + OFF_CPART + tid * 4, pr2));
            float t3 = ld_dsmem(mapa_u32(sb + OFF_CPART + tid * 4, pr3));
            float s = cpart[tid] + t1 + t2 + t3 + c * u512;
            sv[tid] = __fdividef(NORM_C, s);
            if (tid == 0) {
                float sU = wsumP[0] + u512;
                sU += ld_dsmem(mapa_u32(sb + OFF_WSUM, pr1));
                sU += ld_dsmem(mapa_u32(sb + OFF_WSUM, pr2));
                sU += ld_dsmem(mapa_u32(sb + OFF_WSUM, pr3));
                sv[512] = __fdividef(AB512, c * sU);
            }
        }
        __syncthreads();
        if (warp == 0) {
            float p = 0.f;
#pragma unroll
            for (int k = 0; k < 16; ++k) p += sv[lane + 32 * k];
#pragma unroll
            for (int o = 16; o > 0; o >>= 1) p += __shfl_xor_sync(0xffffffffu, p, o);
            if (lane == 0) sscal[0] = __fdividef(AB512, c * (p + sv[512]));
        }
        CLUSTER_SYNC();
    }

    // ---- final pass: last row update + output write ----
    {
#pragma unroll
        for (int q = 0; q < 4; ++q) {
            vr[q]     = *reinterpret_cast<float2*>(&sv[lane * 8 + 2 * q]);
            vr[q + 4] = *reinterpret_cast<float2*>(&sv[256 + lane * 8 + 2 * q]);
        }
        const float v512 = sv[512];
        const float u512 = sscal[0];
        float* og = out + (size_t)g * MA * MA;
#pragma unroll
        for (int b = 0; b < 2; ++b) {
            float rs[4];
#pragma unroll
            for (int r = 0; r < 4; ++r) {
                read_row(lr0 + b * 4 + r, e);
                float s = 0.f;
#pragma unroll
                for (int q = 0; q < 8; ++q) s += e[q].x * vr[q].x + e[q].y * vr[q].y;
                rs[r] = s;
            }
#pragma unroll
            for (int o = 16; o > 0; o >>= 1)
#pragma unroll
                for (int r = 0; r < 4; ++r) rs[r] += __shfl_xor_sync(0xffffffffu, rs[r], o);
#pragma unroll
            for (int r = 0; r < 4; ++r) {
                const int lr = lr0 + b * 4 + r;
                const int i = (int)rank * 128 + lr;
                const float u = __fdividef(NORM_C, rs[r] + c * v512);
                read_row(lr, e);
                float* o0 = og + (size_t)i * MA + lane * 8;
                float* o1 = o0 + 256;
#pragma unroll
                for (int q = 0; q < 4; ++q) {
                    o0[2 * q]     = u * e[q].x * vr[q].x;
                    o0[2 * q + 1] = u * e[q].y * vr[q].y;
                    o1[2 * q]     = u * e[q + 4].x * vr[q + 4].x;
                    o1[2 * q + 1] = u * e[q + 4].y * vr[q + 4].y;
                }
                if (lane == 0) og[(size_t)i * MA + 512] = u * c * v512;
            }
        }
        if (rank == 3) {
            og[(size_t)512 * MA + tid] = u512 * c * sv[tid];
            if (tid == 0) og[(size_t)512 * MA + 512] = u512 * c * v512;
        }
    }
}

// ---------------- launch ----------------
extern "C" void kernel_launch(void* const* d_in, const int* in_sizes, int n_in,
                              void* d_out, int out_size) {
    const float* det   = (const float*)d_in[0];
    const float* tra   = (const float*)d_in[1];
    const float* alpha = (const float*)d_in[2];
    const float* eps   = (const float*)d_in[3];
    float* out = (float*)d_out;

    cudaFuncSetAttribute(fused_kernel, cudaFuncAttributeMaxDynamicSharedMemorySize, SMEM_TOTAL);

    normalize_kernel<<<dim3((G_ * M_) / 8, 2), 256>>>(tra, det);
    fused_kernel<<<dim3(4, G_), 512, SMEM_TOTAL>>>(out, alpha, eps);
}

// round 12
// speedup vs baseline: 1.2125x; 1.2125x over previous
#include <cuda_runtime.h>
#include <cuda_fp16.h>
#include <cstdint>
#include <cstddef>

#define G_   128
#define M_   512
#define D_   512
#define MA   513
#define LD2  512
#define NORM_C (1.0f/1024.0f)
#define VSF  65536.0f          // v stored in fp16 as v*VSF (avoids fp16 subnormals)

// ---------------- scratch ----------------
__device__ __align__(16) __half g_E[(size_t)G_ * M_ * LD2];   // exp(-c/lambda), 64 MB
__device__ __align__(16) __half g_Ah[(size_t)G_ * M_ * D_];   // normalized tra fp16
__device__ __align__(16) __half g_Bh[(size_t)G_ * M_ * D_];   // normalized det fp16
__device__ float g_cs[G_ * 512];                               // gemm-produced colsums

// ---------------- helpers ----------------
__device__ __forceinline__ uint32_t pack_h2(float lo, float hi) {
    uint32_t r; asm("cvt.rn.f16x2.f32 %0, %1, %2;" : "=r"(r) : "f"(hi), "f"(lo)); return r;
}
__device__ __forceinline__ uint32_t s2u(const void* p) {
    return (uint32_t)__cvta_generic_to_shared(p);
}
__device__ __forceinline__ void cp16(uint32_t saddr, const void* g) {
    asm volatile("cp.async.cg.shared.global [%0], [%1], 16;" :: "r"(saddr), "l"(g));
}
__device__ __forceinline__ void ldsm4(uint32_t* r, uint32_t a) {
    asm volatile("ldmatrix.sync.aligned.m8n8.x4.shared.b16 {%0,%1,%2,%3}, [%4];"
                 : "=r"(r[0]), "=r"(r[1]), "=r"(r[2]), "=r"(r[3]) : "r"(a));
}
__device__ __forceinline__ void cvt8(uint4 d0, uint4 d1, float2* e) {
    e[0] = __half22float2(*reinterpret_cast<__half2*>(&d0.x));
    e[1] = __half22float2(*reinterpret_cast<__half2*>(&d0.y));
    e[2] = __half22float2(*reinterpret_cast<__half2*>(&d0.z));
    e[3] = __half22float2(*reinterpret_cast<__half2*>(&d0.w));
    e[4] = __half22float2(*reinterpret_cast<__half2*>(&d1.x));
    e[5] = __half22float2(*reinterpret_cast<__half2*>(&d1.y));
    e[6] = __half22float2(*reinterpret_cast<__half2*>(&d1.z));
    e[7] = __half22float2(*reinterpret_cast<__half2*>(&d1.w));
}

// ---------------- normalize + fp16 convert (+ zero g_cs) ----------------
__global__ void __launch_bounds__(256) normalize_kernel(const float* __restrict__ tra,
                                                        const float* __restrict__ det) {
    if (blockIdx.y == 0 && blockIdx.x < 64) {
        int idx = blockIdx.x * 256 + threadIdx.x;
        for (int k = idx; k < G_ * 512; k += 64 * 256) g_cs[k] = 0.f;
    }
    const float* x = blockIdx.y ? det : tra;
    __half* out = blockIdx.y ? g_Bh : g_Ah;
    int warp = threadIdx.x >> 5, lane = threadIdx.x & 31;
    int row = blockIdx.x * 8 + warp;
    const float4* p = reinterpret_cast<const float4*>(x + (size_t)row * D_);
    float4 v[4];
    float s = 0.f;
#pragma unroll
    for (int k = 0; k < 4; ++k) {
        v[k] = p[lane + k * 32];
        s += v[k].x * v[k].x + v[k].y * v[k].y + v[k].z * v[k].z + v[k].w * v[k].w;
    }
#pragma unroll
    for (int o = 16; o > 0; o >>= 1) s += __shfl_xor_sync(0xffffffffu, s, o);
    float inv = rsqrtf(s);
    uint2* po = reinterpret_cast<uint2*>(out + (size_t)row * D_);
#pragma unroll
    for (int k = 0; k < 4; ++k) {
        uint2 h;
        h.x = pack_h2(v[k].x * inv, v[k].y * inv);
        h.y = pack_h2(v[k].z * inv, v[k].w * inv);
        po[lane + k * 32] = h;
    }
}

// ---------------- fp16 GEMM + exp epilogue + colsum partials ----------------
#define BK 32
#define ROWH 40
#define TILE_H (128 * ROWH)

__global__ void __launch_bounds__(256) gemm_kernel(const float* __restrict__ eps) {
    __shared__ __half sA[2][TILE_H];
    __shared__ __half sB[2][TILE_H];
    const int tid = threadIdx.x;
    const int lane = tid & 31, warp = tid >> 5;
    const int wm = warp >> 2, wn = warp & 3;
    const int grp = lane >> 2, tig = lane & 3;
    const int g = blockIdx.z;
    const int m0 = blockIdx.y * 128, n0 = blockIdx.x * 128;
    const __half* gA = g_Ah + (size_t)(g * M_ + m0) * D_;
    const __half* gB = g_Bh + (size_t)(g * M_ + n0) * D_;
    const uint32_t sAu = s2u(sA), sBu = s2u(sB);

    const int aRow = (((lane >> 3) & 1) << 3) + (lane & 7);
    const int aCol = ((lane >> 4) << 3);
    const int bRow = ((lane >> 4) << 3) + (lane & 7);
    const int bCol = (((lane >> 3) & 1) << 3);

    float acc[4][4][4];
#pragma unroll
    for (int a = 0; a < 4; ++a)
#pragma unroll
        for (int b = 0; b < 4; ++b)
#pragma unroll
            for (int c = 0; c < 4; ++c) acc[a][b][c] = 0.f;

    const int lrow = tid >> 2, lc = tid & 3;
    auto load = [&](int kc, int buf) {
        const __half* a = gA + kc * BK;
        const __half* b = gB + kc * BK;
#pragma unroll
        for (int t = 0; t < 2; ++t) {
            int row = lrow + t * 64;
            cp16(sAu + (buf * TILE_H + row * ROWH) * 2 + lc * 16, a + (size_t)row * D_ + lc * 8);
            cp16(sBu + (buf * TILE_H + row * ROWH) * 2 + lc * 16, b + (size_t)row * D_ + lc * 8);
        }
        asm volatile("cp.async.commit_group;" ::: "memory");
    };

    load(0, 0);
    const int NKT = D_ / BK;
    for (int kt = 0; kt < NKT; ++kt) {
        asm volatile("cp.async.wait_group 0;" ::: "memory");
        __syncthreads();
        if (kt + 1 < NKT) load(kt + 1, (kt + 1) & 1);
        const int buf = kt & 1;
        const uint32_t ab = sAu + (buf * TILE_H) * 2;
        const uint32_t bb = sBu + (buf * TILE_H) * 2;
#pragma unroll
        for (int ks = 0; ks < 2; ++ks) {
            uint32_t af[4][4], bf[2][4];
#pragma unroll
            for (int mt = 0; mt < 4; ++mt)
                ldsm4(af[mt], ab + ((wm * 64 + mt * 16 + aRow) * ROWH + ks * 16 + aCol) * 2);
#pragma unroll
            for (int p = 0; p < 2; ++p)
                ldsm4(bf[p], bb + ((wn * 32 + p * 16 + bRow) * ROWH + ks * 16 + bCol) * 2);
#pragma unroll
            for (int mt = 0; mt < 4; ++mt)
#pragma unroll
                for (int nt = 0; nt < 4; ++nt)
                    asm volatile(
                        "mma.sync.aligned.m16n8k16.row.col.f32.f16.f16.f32 "
                        "{%0,%1,%2,%3}, {%4,%5,%6,%7}, {%8,%9}, {%0,%1,%2,%3};"
                        : "+f"(acc[mt][nt][0]), "+f"(acc[mt][nt][1]),
                          "+f"(acc[mt][nt][2]), "+f"(acc[mt][nt][3])
                        : "r"(af[mt][0]), "r"(af[mt][1]), "r"(af[mt][2]), "r"(af[mt][3]),
                          "r"(bf[nt >> 1][(nt & 1) * 2]), "r"(bf[nt >> 1][(nt & 1) * 2 + 1]));
        }
    }

    const float invL = 1.0f / (__expf(eps[0]) + 0.03f);
    __half* Eg = g_E + (size_t)g * M_ * LD2;
    float colp[8];
#pragma unroll
    for (int q = 0; q < 8; ++q) colp[q] = 0.f;
#pragma unroll
    for (int mt = 0; mt < 4; ++mt) {
        int m = m0 + wm * 64 + mt * 16 + grp;
#pragma unroll
        for (int nt = 0; nt < 4; ++nt) {
            int n = n0 + wn * 32 + nt * 8 + 2 * tig;
            float ex0 = __expf(-acc[mt][nt][0] * invL);
            float ex1 = __expf(-acc[mt][nt][1] * invL);
            float ex2 = __expf(-acc[mt][nt][2] * invL);
            float ex3 = __expf(-acc[mt][nt][3] * invL);
            *reinterpret_cast<uint32_t*>(&Eg[(size_t)m * LD2 + n])       = pack_h2(ex0, ex1);
            *reinterpret_cast<uint32_t*>(&Eg[(size_t)(m + 8) * LD2 + n]) = pack_h2(ex2, ex3);
            colp[2 * nt]     += ex0 + ex2;
            colp[2 * nt + 1] += ex1 + ex3;
        }
    }
    // column partial sums: smem reduce then one global atomicAdd per column
    __syncthreads();
    float* cp = reinterpret_cast<float*>(sA);
    if (tid < 128) cp[tid] = 0.f;
    __syncthreads();
#pragma unroll
    for (int nt = 0; nt < 4; ++nt) {
        atomicAdd(&cp[wn * 32 + nt * 8 + 2 * tig],     colp[2 * nt]);
        atomicAdd(&cp[wn * 32 + nt * 8 + 2 * tig + 1], colp[2 * nt + 1]);
    }
    __syncthreads();
    if (tid < 128) atomicAdd(&g_cs[g * 512 + n0 + tid], cp[tid]);
}

// ---------------- fused Sinkhorn: 8 E-sweeps, h2 inner math, bins analytic ----------------
__global__ void __launch_bounds__(512, 1) sinkhorn_kernel(
    float* __restrict__ out, const float* __restrict__ alpha, const float* __restrict__ eps)
{
    __shared__ float sv[520];
    __shared__ uint32_t svh[260];     // v * VSF as half2 pairs
    __shared__ float swsum[16];
    __shared__ float sscal[8];
    __shared__ float scol[16 * 512];
    const int g = blockIdx.x, tid = threadIdx.x, w = tid >> 5, lane = tid & 31;
    const __half* Eg = g_E + (size_t)g * M_ * LD2;
    const float invL = 1.f / (__expf(eps[0]) + 0.03f);
    const float cc = __expf(-alpha[0] * invL);
    const float AB512 = NORM_C * 512.f;
    const float NCVS = NORM_C * VSF;
    const int row0 = w * 32;

    // ---- initial v from gemm-computed colsums (u == 1) ----
    {
        float s = g_cs[g * 512 + tid] + cc;
        sv[tid] = __fdividef(NORM_C, s);
        if (tid == 0) sv[512] = __fdividef(AB512, cc * 513.f);
    }
    __syncthreads();
    if (w == 0) {
        float p = 0.f;
#pragma unroll
        for (int k = 0; k < 16; ++k) p += sv[lane + 32 * k];
#pragma unroll
        for (int o = 16; o > 0; o >>= 1) p += __shfl_xor_sync(0xffffffffu, p, o);
        if (lane == 0) sscal[0] = __fdividef(AB512, cc * (p + sv[512]));
    }
    if (tid < 256) svh[tid] = pack_h2(sv[2 * tid] * VSF, sv[2 * tid + 1] * VSF);
    __syncthreads();

    // ---- 7 fused passes: row update + next col accumulation, one E read ----
    for (int it = 0; it < 7; ++it) {
        __half2 hv[8];
#pragma unroll
        for (int q = 0; q < 4; ++q) {
            hv[q]     = *reinterpret_cast<__half2*>(&svh[lane * 4 + q]);
            hv[4 + q] = *reinterpret_cast<__half2*>(&svh[128 + lane * 4 + q]);
        }
        const float v512 = sv[512];
        const float u512 = sscal[0];
        const float cv512s = cc * v512 * VSF;
        __half2 cah[8];
        float ca32[16];
#pragma unroll
        for (int q = 0; q < 8; ++q) cah[q] = __float2half2_rn(0.f);
#pragma unroll
        for (int q = 0; q < 16; ++q) ca32[q] = 0.f;
        float wsum = 0.f;

#pragma unroll 2
        for (int t = 0; t < 16; ++t) {
            const int i = row0 + 2 * t;
            const uint4* rp0 = reinterpret_cast<const uint4*>(Eg + (size_t)i * LD2);
            const uint4* rp1 = reinterpret_cast<const uint4*>(Eg + (size_t)(i + 1) * LD2);
            uint4 d00 = rp0[lane], d01 = rp0[32 + lane];
            uint4 d10 = rp1[lane], d11 = rp1[32 + lane];
            const __half2* e0a = reinterpret_cast<const __half2*>(&d00);
            const __half2* e0b = reinterpret_cast<const __half2*>(&d01);
            const __half2* e1a = reinterpret_cast<const __half2*>(&d10);
            const __half2* e1b = reinterpret_cast<const __half2*>(&d11);
            // rowsum in h2 (16 cols/thread), then fp32 across lanes
            __half2 s0 = __hmul2(e0a[0], hv[0]);
            __half2 s1 = __hmul2(e1a[0], hv[0]);
#pragma unroll
            for (int q = 1; q < 4; ++q) {
                s0 = __hfma2(e0a[q], hv[q], s0);
                s1 = __hfma2(e1a[q], hv[q], s1);
            }
#pragma unroll
            for (int q = 0; q < 4; ++q) {
                s0 = __hfma2(e0b[q], hv[4 + q], s0);
                s1 = __hfma2(e1b[q], hv[4 + q], s1);
            }
            float2 f0 = __half22float2(s0), f1 = __half22float2(s1);
            float rs0 = f0.x + f0.y, rs1 = f1.x + f1.y;
#pragma unroll
            for (int o = 16; o > 0; o >>= 1) {
                rs0 += __shfl_xor_sync(0xffffffffu, rs0, o);
                rs1 += __shfl_xor_sync(0xffffffffu, rs1, o);
            }
            float u0 = __fdividef(NCVS, rs0 + cv512s);
            float u1 = __fdividef(NCVS, rs1 + cv512s);
            wsum += u0 + u1;
            __half2 u0h = __float2half2_rn(u0);
            __half2 u1h = __float2half2_rn(u1);
#pragma unroll
            for (int q = 0; q < 4; ++q) {
                cah[q]     = __hfma2(e0a[q], u0h, cah[q]);
                cah[4 + q] = __hfma2(e0b[q], u0h, cah[4 + q]);
            }
#pragma unroll
            for (int q = 0; q < 4; ++q) {
                cah[q]     = __hfma2(e1a[q], u1h, cah[q]);
                cah[4 + q] = __hfma2(e1b[q], u1h, cah[4 + q]);
            }
            if (t & 1) {   // flush every 4 rows to fp32
#pragma unroll
                for (int q = 0; q < 8; ++q) {
                    float2 f = __half22float2(cah[q]);
                    ca32[2 * q] += f.x; ca32[2 * q + 1] += f.y;
                    cah[q] = __float2half2_rn(0.f);
                }
            }
        }
        {
            float* d0 = scol + w * 512 + lane * 8;
            float* d1 = d0 + 256;
#pragma unroll
            for (int q = 0; q < 4; ++q) {
                d0[2 * q] = ca32[2 * q];         d0[2 * q + 1] = ca32[2 * q + 1];
                d1[2 * q] = ca32[8 + 2 * q];     d1[2 * q + 1] = ca32[8 + 2 * q + 1];
            }
        }
        if (lane == 0) swsum[w] = wsum;
        __syncthreads();
        {
            float s = cc * u512;
#pragma unroll
            for (int ww = 0; ww < 16; ++ww) s += scol[ww * 512 + tid];
            sv[tid] = __fdividef(NORM_C, s);
            if (tid == 0) {
                float sU = u512;
#pragma unroll
                for (int ww = 0; ww < 16; ++ww) sU += swsum[ww];
                sv[512] = __fdividef(AB512, cc * sU);
            }
        }
        __syncthreads();
        if (w == 0) {
            float p = 0.f;
#pragma unroll
            for (int k = 0; k < 16; ++k) p += sv[lane + 32 * k];
#pragma unroll
            for (int o = 16; o > 0; o >>= 1) p += __shfl_xor_sync(0xffffffffu, p, o);
            if (lane == 0) sscal[0] = __fdividef(AB512, cc * (p + sv[512]));
        }
        if (tid < 256) svh[tid] = pack_h2(sv[2 * tid] * VSF, sv[2 * tid + 1] * VSF);
        __syncthreads();
    }

    // ---- final pass: last row update + output write (fp32 path) ----
    {
        float2 vr[8];
#pragma unroll
        for (int q = 0; q < 4; ++q) {
            vr[q]     = *reinterpret_cast<float2*>(&sv[lane * 8 + 2 * q]);
            vr[q + 4] = *reinterpret_cast<float2*>(&sv[256 + lane * 8 + 2 * q]);
        }
        const float v512 = sv[512];
        const float u512 = sscal[0];
        float* og = out + (size_t)g * MA * MA;
#pragma unroll 2
        for (int t = 0; t < 32; ++t) {
            const int i = row0 + t;
            const uint4* rp = reinterpret_cast<const uint4*>(Eg + (size_t)i * LD2);
            uint4 d0 = rp[lane], d1 = rp[32 + lane];
            float2 e[8];
            cvt8(d0, d1, e);
            float rs = 0.f;
#pragma unroll
            for (int q = 0; q < 8; ++q) rs += e[q].x * vr[q].x + e[q].y * vr[q].y;
#pragma unroll
            for (int o = 16; o > 0; o >>= 1) rs += __shfl_xor_sync(0xffffffffu, rs, o);
            const float u = __fdividef(NORM_C, rs + cc * v512);
            float* o0 = og + (size_t)i * MA + lane * 8;
            float* o1 = o0 + 256;
#pragma unroll
            for (int q = 0; q < 4; ++q) {
                o0[2 * q]     = u * e[q].x * vr[q].x;
                o0[2 * q + 1] = u * e[q].y * vr[q].y;
                o1[2 * q]     = u * e[q + 4].x * vr[q + 4].x;
                o1[2 * q + 1] = u * e[q + 4].y * vr[q + 4].y;
            }
            if (lane == 0) og[(size_t)i * MA + 512] = u * cc * v512;
        }
        og[(size_t)512 * MA + tid] = u512 * cc * sv[tid];
        if (tid == 0) og[(size_t)512 * MA + 512] = u512 * cc * v512;
    }
}

// ---------------- launch ----------------
extern "C" void kernel_launch(void* const* d_in, const int* in_sizes, int n_in,
                              void* d_out, int out_size) {
    const float* det   = (const float*)d_in[0];
    const float* tra   = (const float*)d_in[1];
    const float* alpha = (const float*)d_in[2];
    const float* eps   = (const float*)d_in[3];
    float* out = (float*)d_out;

    normalize_kernel<<<dim3((G_ * M_) / 8, 2), 256>>>(tra, det);
    gemm_kernel<<<dim3(4, 4, G_), 256>>>(eps);
    sinkhorn_kernel<<<G_, 512>>>(out, alpha, eps);
}